// round 2
// baseline (speedup 1.0000x reference)
#include <cuda_runtime.h>

// Problem constants (fixed by this problem's shapes)
#define DD 64
#define HH 256
#define TILE 64
#define MAXG 4096
#define BN_EPS 1e-3f

// Scratch for per-graph pooled sums (no cudaMalloc allowed)
__device__ float g_pooled[MAXG * DD];

__device__ __forceinline__ float tanh_fast(float x) {
    float r;
    asm("tanh.approx.f32 %0, %1;" : "=f"(r) : "f"(x));
    return r;
}
__device__ __forceinline__ float sigmoid_fast(float x) {
    // 1 / (1 + exp(-x)) via ex2.approx (inside __expf)
    return 1.0f / (1.0f + __expf(-x));
}

__global__ void zero_pooled_kernel(int n) {
    for (int i = blockIdx.x * blockDim.x + threadIdx.x; i < n; i += gridDim.x * blockDim.x)
        g_pooled[i] = 0.0f;
}

// Node-stage kernel: per-node gated dense + sorted segment-sum.
//   P[n][c] = sum_k h[n][k]*A[k][c] + sum_k x[n][k]*B[k][c]   (A = W_i[0:64], B = W_i[64:128])
//   J[n][c] = sum_k h[n][k]*Wj[k][c]
//   RR      = sigmoid(tanh(P + b_i)) * relu(J + b_j)
//   pooled[seg][c] += RR[n][c]   (segment_ids sorted -> run-length flush + atomicAdd)
extern __shared__ float s_dyn[];

__global__ __launch_bounds__(256, 2) void node_kernel(
    const float* __restrict__ x, const float* __restrict__ h,
    const float* __restrict__ W_i, const float* __restrict__ b_i,
    const float* __restrict__ W_j, const float* __restrict__ b_j,
    const int* __restrict__ seg_ids, int N, int ntiles)
{
    float* sA  = s_dyn;                 // 64*64
    float* sB  = sA + 64 * 64;          // 64*64
    float* sW  = sB + 64 * 64;          // 64*64
    float* sh  = sW + 64 * 64;          // 64*65 (padded)
    float* sx  = sh + 64 * 65;          // 64*65 (padded)
    float* srr = sx + 64 * 65;          // 64*64
    int*   sseg = (int*)(srr + 64 * 64);// 64

    const int tid = threadIdx.x;
    const int tx = tid & 15;            // column group: cols [4*tx, 4*tx+3]
    const int ty = tid >> 4;            // node group:   rows [4*ty, 4*ty+3]

    // Stage weights once per block
    for (int i = tid; i < 64 * 64; i += 256) {
        sA[i] = W_i[i];
        sB[i] = W_i[64 * 64 + i];
        sW[i] = W_j[i];
    }
    float bi[4], bj[4];
#pragma unroll
    for (int c = 0; c < 4; c++) {
        bi[c] = b_i[4 * tx + c];
        bj[c] = b_j[4 * tx + c];
    }
    __syncthreads();

    for (int tile = blockIdx.x; tile < ntiles; tile += gridDim.x) {
        const int base = tile * TILE;

        // Load h, x tile (coalesced), zero-pad past N
        for (int i = tid; i < TILE * 64; i += 256) {
            const int n = i >> 6, k = i & 63;
            const int gn = base + n;
            float hv = 0.0f, xv = 0.0f;
            if (gn < N) {
                hv = h[(size_t)gn * 64 + k];
                xv = x[(size_t)gn * 64 + k];
            }
            sh[n * 65 + k] = hv;
            sx[n * 65 + k] = xv;
        }
        if (tid < TILE) {
            const int gn = base + tid;
            sseg[tid] = (gn < N) ? seg_ids[gn] : -1;
        }
        __syncthreads();

        float P[4][4], J[4][4];
#pragma unroll
        for (int i = 0; i < 4; i++)
#pragma unroll
            for (int c = 0; c < 4; c++) { P[i][c] = 0.0f; J[i][c] = 0.0f; }

        // h contributes to both P (via A) and J (via Wj)
#pragma unroll 8
        for (int k = 0; k < 64; k++) {
            const float4 a = reinterpret_cast<const float4*>(sA + k * 64)[tx];
            const float4 w = reinterpret_cast<const float4*>(sW + k * 64)[tx];
#pragma unroll
            for (int i = 0; i < 4; i++) {
                const float hv = sh[(4 * ty + i) * 65 + k];
                P[i][0] = fmaf(hv, a.x, P[i][0]);
                P[i][1] = fmaf(hv, a.y, P[i][1]);
                P[i][2] = fmaf(hv, a.z, P[i][2]);
                P[i][3] = fmaf(hv, a.w, P[i][3]);
                J[i][0] = fmaf(hv, w.x, J[i][0]);
                J[i][1] = fmaf(hv, w.y, J[i][1]);
                J[i][2] = fmaf(hv, w.z, J[i][2]);
                J[i][3] = fmaf(hv, w.w, J[i][3]);
            }
        }
        // x contributes to P via B
#pragma unroll 8
        for (int k = 0; k < 64; k++) {
            const float4 b = reinterpret_cast<const float4*>(sB + k * 64)[tx];
#pragma unroll
            for (int i = 0; i < 4; i++) {
                const float xv = sx[(4 * ty + i) * 65 + k];
                P[i][0] = fmaf(xv, b.x, P[i][0]);
                P[i][1] = fmaf(xv, b.y, P[i][1]);
                P[i][2] = fmaf(xv, b.z, P[i][2]);
                P[i][3] = fmaf(xv, b.w, P[i][3]);
            }
        }

        // Epilogue: activations -> RR into smem
#pragma unroll
        for (int i = 0; i < 4; i++) {
            float4 rr;
            float iv, jv;
            iv = tanh_fast(P[i][0] + bi[0]); jv = fmaxf(J[i][0] + bj[0], 0.0f); rr.x = sigmoid_fast(iv) * jv;
            iv = tanh_fast(P[i][1] + bi[1]); jv = fmaxf(J[i][1] + bj[1], 0.0f); rr.y = sigmoid_fast(iv) * jv;
            iv = tanh_fast(P[i][2] + bi[2]); jv = fmaxf(J[i][2] + bj[2], 0.0f); rr.z = sigmoid_fast(iv) * jv;
            iv = tanh_fast(P[i][3] + bi[3]); jv = fmaxf(J[i][3] + bj[3], 0.0f); rr.w = sigmoid_fast(iv) * jv;
            reinterpret_cast<float4*>(srr + (4 * ty + i) * 64)[tx] = rr;
        }
        __syncthreads();

        // Sorted-segment run-length reduction: thread (r, c) sums nodes [16r,16r+16) col c
        {
            const int c = tid & 63;
            const int r = tid >> 6;
            const int n0 = r * 16;
            float acc = 0.0f;
            int cur = sseg[n0];
#pragma unroll 4
            for (int n = n0; n < n0 + 16; n++) {
                const int s = sseg[n];
                if (s != cur) {
                    if (cur >= 0) atomicAdd(&g_pooled[cur * DD + c], acc);
                    acc = 0.0f;
                    cur = s;
                }
                acc += srr[n * 64 + c];
            }
            if (cur >= 0) atomicAdd(&g_pooled[cur * DD + c], acc);
        }
        __syncthreads();  // protect sh/sx/sseg/srr before next tile
    }
}

// Per-graph readout: BN(inference) -> Dense(64->256)+ReLU -> Dense(256->1)
__global__ void readout_kernel(
    const float* __restrict__ gamma, const float* __restrict__ beta,
    const float* __restrict__ mov_mean, const float* __restrict__ mov_var,
    const float* __restrict__ W_h1, const float* __restrict__ b_h1,
    const float* __restrict__ W_out, const float* __restrict__ b_out,
    float* __restrict__ out)
{
    __shared__ float bn[DD];
    __shared__ float warp_part[8];
    const int g = blockIdx.x;
    const int t = threadIdx.x;

    if (t < DD) {
        const float p = g_pooled[g * DD + t];
        bn[t] = (p - mov_mean[t]) * rsqrtf(mov_var[t] + BN_EPS) * gamma[t] + beta[t];
    }
    __syncthreads();

    float y = 0.0f;
#pragma unroll 8
    for (int d = 0; d < DD; d++)
        y = fmaf(bn[d], W_h1[d * HH + t], y);
    y = fmaxf(y + b_h1[t], 0.0f);

    float v = y * W_out[t];
#pragma unroll
    for (int o = 16; o > 0; o >>= 1) v += __shfl_xor_sync(0xffffffffu, v, o);
    if ((t & 31) == 0) warp_part[t >> 5] = v;
    __syncthreads();
    if (t < 32) {
        float s = (t < 8) ? warp_part[t] : 0.0f;
#pragma unroll
        for (int o = 4; o > 0; o >>= 1) s += __shfl_xor_sync(0xffffffffu, s, o);
        if (t == 0) out[g] = s + b_out[0];
    }
}

extern "C" void kernel_launch(void* const* d_in, const int* in_sizes, int n_in,
                              void* d_out, int out_size)
{
    const float* x        = (const float*)d_in[0];
    const float* h        = (const float*)d_in[1];
    const float* W_i      = (const float*)d_in[2];
    const float* b_i      = (const float*)d_in[3];
    const float* W_j      = (const float*)d_in[4];
    const float* b_j      = (const float*)d_in[5];
    const float* gamma    = (const float*)d_in[6];
    const float* beta     = (const float*)d_in[7];
    const float* mov_mean = (const float*)d_in[8];
    const float* mov_var  = (const float*)d_in[9];
    const float* W_h1     = (const float*)d_in[10];
    const float* b_h1     = (const float*)d_in[11];
    const float* W_out    = (const float*)d_in[12];
    const float* b_out    = (const float*)d_in[13];
    const int*   seg      = (const int*)d_in[14];

    const int N = in_sizes[14];        // segment_ids element count = node count
    const int G = out_size;            // out is [G, 1]
    const int ntiles = (N + TILE - 1) / TILE;

    // (1) zero pooled scratch
    zero_pooled_kernel<<<256, 256>>>(G * DD);

    // (2) node stage (persistent-ish grid, ~2 blocks/SM)
    const size_t smem_bytes =
        (size_t)(3 * 64 * 64 + 2 * 64 * 65 + 64 * 64) * sizeof(float) + 64 * sizeof(int);
    cudaFuncSetAttribute(node_kernel, cudaFuncAttributeMaxDynamicSharedMemorySize,
                         (int)smem_bytes);
    int grid = 296;
    if (grid > ntiles) grid = ntiles;
    node_kernel<<<grid, 256, smem_bytes>>>(x, h, W_i, b_i, W_j, b_j, seg, N, ntiles);

    // (3) per-graph BN + MLP readout
    readout_kernel<<<G, 256>>>(gamma, beta, mov_mean, mov_var, W_h1, b_h1, W_out, b_out,
                               (float*)d_out);
}

// round 4
// speedup vs baseline: 2.8749x; 2.8749x over previous
#include <cuda_runtime.h>

#define DD 64
#define HH 256
#define MAXG 4096
#define BN_EPS 1e-3f
#define NT 64            // nodes per tile (GEMM M)
#define KK 128           // K dim ([h|x])
#define ASTRIDE 132      // A smem row stride in floats (128 + 4 pad)

__device__ float g_pooled[MAXG * DD];

// ---------- shared memory byte map (dynamic) ----------
#define SM_A0   0            // A buf 0: 64 x 132 fp32 = 33792 B
#define SM_A1   33792        // A buf 1
#define SM_RR   67584        // RR staging: 64 x 68 fp32 = 17408 B
#define SM_BI   84992        // b_i (64 f)
#define SM_BJ   85248        // b_j (64 f)
#define SM_SEG  85504        // 64 ints
#define SM_TOTAL 85760

__device__ __forceinline__ float tanh_fast(float v) {
    float r;
    asm("tanh.approx.f32 %0, %1;" : "=f"(r) : "f"(v));
    return r;
}
__device__ __forceinline__ unsigned int f2tf32(float v) {
    unsigned int u;
    asm("cvt.rna.tf32.f32 %0, %1;" : "=r"(u) : "f"(v));
    return u;
}
__device__ __forceinline__ void mma_tf32(float* c, const unsigned int* a,
                                         const unsigned int* b) {
    asm volatile(
        "mma.sync.aligned.m16n8k8.row.col.f32.tf32.tf32.f32 "
        "{%0,%1,%2,%3}, {%4,%5,%6,%7}, {%8,%9}, {%0,%1,%2,%3};"
        : "+f"(c[0]), "+f"(c[1]), "+f"(c[2]), "+f"(c[3])
        : "r"(a[0]), "r"(a[1]), "r"(a[2]), "r"(a[3]), "r"(b[0]), "r"(b[1]));
}

__global__ void zero_pooled_kernel(int n) {
    for (int i = blockIdx.x * blockDim.x + threadIdx.x; i < n; i += gridDim.x * blockDim.x)
        g_pooled[i] = 0.0f;
}

extern __shared__ char smc[];

__global__ __launch_bounds__(256, 1) void node_mma_kernel(
    const float* __restrict__ x, const float* __restrict__ h,
    const float* __restrict__ W_i, const float* __restrict__ b_i,
    const float* __restrict__ W_j, const float* __restrict__ b_j,
    const int* __restrict__ seg, int N, int ntiles)
{
    const int tid  = threadIdx.x;
    const int w    = tid >> 5, lane = tid & 31;
    const int wm   = w >> 2;          // 0..1 : row block of 32
    const int wn   = w & 3;           // 0..3 : B-col block of 32
    const int lr   = lane >> 2;       // 0..7
    const int lc   = lane & 3;        // 0..3

    float* sA0 = (float*)(smc + SM_A0);
    float* sA1 = (float*)(smc + SM_A1);
    float* srr = (float*)(smc + SM_RR);
    float* sbi = (float*)(smc + SM_BI);
    float* sbj = (float*)(smc + SM_BJ);
    int*  sseg = (int*)(smc + SM_SEG);

    if (tid < 64) {
        sbi[tid] = b_i[tid];
        sbj[tid] = b_j[tid];
    }

    // ---- Weight-stationary B fragments (tf32, rna-rounded), once per CTA ----
    // B[n][k], n in [wn*32, wn*32+32): even n -> W_i col n/2 (k 0..127),
    //                                  odd n  -> W_j col n/2 (k<64) else 0.
    unsigned int Bf[4][16][2];
#pragma unroll
    for (int nf = 0; nf < 4; nf++) {
        const int n = wn * 32 + nf * 8 + lr;
        const int pcol = n >> 1;
        const bool isP = (n & 1) == 0;
#pragma unroll
        for (int ks = 0; ks < 16; ks++) {
#pragma unroll
            for (int i = 0; i < 2; i++) {
                const int k = ks * 8 + lc + i * 4;
                float v;
                if (isP)          v = W_i[k * 64 + pcol];
                else if (k < 64)  v = W_j[k * 64 + pcol];
                else              v = 0.0f;
                Bf[nf][ks][i] = f2tf32(v);
            }
        }
    }

    // ---- cp.async tile loader: A[node][k] = k<64 ? h : x ----
    auto load_tile = [&](int tile, int buf) {
        if (tile < ntiles) {
            float* ab = buf ? sA1 : sA0;
            const int base = tile * NT;
#pragma unroll
            for (int j = 0; j < 8; j++) {
                const int idx = tid + j * 256;      // 0..2047 float4 chunks
                const int n = idx >> 5, kc = (idx & 31) << 2;
                const int gn = base + n;
                const float* src = (kc < 64) ? (h + (size_t)gn * 64 + kc)
                                             : (x + (size_t)gn * 64 + (kc - 64));
                const int nb = (gn < N) ? 16 : 0;
                unsigned int dst;
                asm("{ .reg .u64 t; cvta.to.shared.u64 t, %1; cvt.u32.u64 %0, t; }"
                    : "=r"(dst) : "l"(ab + n * ASTRIDE + kc));
                asm volatile("cp.async.cg.shared.global [%0], [%1], 16, %2;"
                             :: "r"(dst), "l"(src), "r"(nb) : "memory");
            }
        }
        asm volatile("cp.async.commit_group;" ::: "memory");
    };

    load_tile(blockIdx.x, 0);
    load_tile(blockIdx.x + gridDim.x, 1);
    __syncthreads();   // covers sbi/sbj too

    for (int it = 0;; it++) {
        const int tile = blockIdx.x + it * gridDim.x;
        if (tile >= ntiles) break;
        const int buf = it & 1;
        float* sA = buf ? sA1 : sA0;

        asm volatile("cp.async.wait_group 1;" ::: "memory");
        __syncthreads();

        // Stage segment ids for this tile
        if (tid < NT) {
            const int gn = tile * NT + tid;
            sseg[tid] = (gn < N) ? seg[gn] : -1;
        }

        // ---- GEMM: warp computes rows [wm*32, +32) x B-cols [wn*32, +32) ----
        float C[2][4][4];
#pragma unroll
        for (int mf = 0; mf < 2; mf++)
#pragma unroll
            for (int nf = 0; nf < 4; nf++)
#pragma unroll
                for (int q = 0; q < 4; q++) C[mf][nf][q] = 0.0f;

#pragma unroll
        for (int ks = 0; ks < 16; ks++) {
            unsigned int a[2][4];
#pragma unroll
            for (int mf = 0; mf < 2; mf++) {
                const float* p = sA + (wm * 32 + mf * 16 + lr) * ASTRIDE + ks * 8 + lc;
                a[mf][0] = __float_as_uint(p[0]);
                a[mf][1] = __float_as_uint(p[8 * ASTRIDE]);
                a[mf][2] = __float_as_uint(p[4]);
                a[mf][3] = __float_as_uint(p[8 * ASTRIDE + 4]);
            }
#pragma unroll
            for (int nf = 0; nf < 4; nf++) {
#pragma unroll
                for (int mf = 0; mf < 2; mf++)
                    mma_tf32(C[mf][nf], a[mf], Bf[nf][ks]);
            }
        }

        // ---- Epilogue in registers: (c_even, c_odd) = (P, J) same node/col ----
#pragma unroll
        for (int nf = 0; nf < 4; nf++) {
            const int pcol = wn * 16 + nf * 4 + lc;
            const float bi = sbi[pcol], bj = sbj[pcol];
#pragma unroll
            for (int mf = 0; mf < 2; mf++) {
                const int r0 = wm * 32 + mf * 16 + lr;
#pragma unroll
                for (int rp = 0; rp < 2; rp++) {
                    const float P = C[mf][nf][rp * 2] + bi;
                    const float J = C[mf][nf][rp * 2 + 1] + bj;
                    const float iv = tanh_fast(P);
                    const float s = fmaf(tanh_fast(0.5f * iv), 0.5f, 0.5f); // sigmoid
                    srr[(r0 + rp * 8) * 68 + pcol] = s * fmaxf(J, 0.0f);
                }
            }
        }
        __syncthreads();

        // Prefetch tile it+2 into the just-consumed buffer (overlaps reduce)
        load_tile(blockIdx.x + (it + 2) * gridDim.x, buf);

        // ---- Sorted-segment run-length reduce: thread (r,c) sums 16 nodes ----
        {
            const int c = tid & 63, r = tid >> 6;
            const int n0 = r * 16;
            float acc = 0.0f;
            int cur = sseg[n0];
#pragma unroll 4
            for (int n = n0; n < n0 + 16; n++) {
                const int s = sseg[n];
                if (s != cur) {
                    if (cur >= 0) atomicAdd(&g_pooled[cur * DD + c], acc);
                    acc = 0.0f;
                    cur = s;
                }
                acc += srr[n * 68 + c];
            }
            if (cur >= 0) atomicAdd(&g_pooled[cur * DD + c], acc);
        }
        __syncthreads();
    }

    asm volatile("cp.async.wait_group 0;" ::: "memory");
}

// Per-graph readout: BN(inference) -> Dense(64->256)+ReLU -> Dense(256->1)
__global__ void readout_kernel(
    const float* __restrict__ gamma, const float* __restrict__ beta,
    const float* __restrict__ mov_mean, const float* __restrict__ mov_var,
    const float* __restrict__ W_h1, const float* __restrict__ b_h1,
    const float* __restrict__ W_out, const float* __restrict__ b_out,
    float* __restrict__ out)
{
    __shared__ float bn[DD];
    __shared__ float warp_part[8];
    const int g = blockIdx.x;
    const int t = threadIdx.x;

    if (t < DD) {
        const float p = g_pooled[g * DD + t];
        bn[t] = (p - mov_mean[t]) * rsqrtf(mov_var[t] + BN_EPS) * gamma[t] + beta[t];
    }
    __syncthreads();

    float y = 0.0f;
#pragma unroll 8
    for (int d = 0; d < DD; d++)
        y = fmaf(bn[d], W_h1[d * HH + t], y);
    y = fmaxf(y + b_h1[t], 0.0f);

    float v = y * W_out[t];
#pragma unroll
    for (int o = 16; o > 0; o >>= 1) v += __shfl_xor_sync(0xffffffffu, v, o);
    if ((t & 31) == 0) warp_part[t >> 5] = v;
    __syncthreads();
    if (t < 32) {
        float s = (t < 8) ? warp_part[t] : 0.0f;
#pragma unroll
        for (int o = 4; o > 0; o >>= 1) s += __shfl_xor_sync(0xffffffffu, s, o);
        if (t == 0) out[g] = s + b_out[0];
    }
}

extern "C" void kernel_launch(void* const* d_in, const int* in_sizes, int n_in,
                              void* d_out, int out_size)
{
    const float* x        = (const float*)d_in[0];
    const float* h        = (const float*)d_in[1];
    const float* W_i      = (const float*)d_in[2];
    const float* b_i      = (const float*)d_in[3];
    const float* W_j      = (const float*)d_in[4];
    const float* b_j      = (const float*)d_in[5];
    const float* gamma    = (const float*)d_in[6];
    const float* beta     = (const float*)d_in[7];
    const float* mov_mean = (const float*)d_in[8];
    const float* mov_var  = (const float*)d_in[9];
    const float* W_h1     = (const float*)d_in[10];
    const float* b_h1     = (const float*)d_in[11];
    const float* W_out    = (const float*)d_in[12];
    const float* b_out    = (const float*)d_in[13];
    const int*   seg      = (const int*)d_in[14];

    const int N = in_sizes[14];
    const int G = out_size;
    const int ntiles = (N + NT - 1) / NT;

    zero_pooled_kernel<<<256, 256>>>(G * DD);

    cudaFuncSetAttribute(node_mma_kernel, cudaFuncAttributeMaxDynamicSharedMemorySize,
                         SM_TOTAL);
    int grid = 148;
    if (grid > ntiles) grid = ntiles;
    node_mma_kernel<<<grid, 256, SM_TOTAL>>>(x, h, W_i, b_i, W_j, b_j, seg, N, ntiles);

    readout_kernel<<<G, 256>>>(gamma, beta, mov_mean, mov_var, W_h1, b_h1, W_out, b_out,
                               (float*)d_out);
}

// round 5
// speedup vs baseline: 3.5505x; 1.2350x over previous
#include <cuda_runtime.h>
#include <cuda_fp16.h>

#define DD 64
#define HH 256
#define MAXG 4096
#define BN_EPS 1e-3f
#define NT 64            // nodes per tile (GEMM M)
#define AST 136          // A smem row stride in halves (128 + 8 pad -> 272B)

__device__ float g_pooled[MAXG * DD];

// ---------- shared memory byte map (dynamic) ----------
#define SM_A0   0            // A buf 0: 64 x 136 fp16 = 17408 B
#define SM_A1   17408        // A buf 1
#define SM_RR   34816        // RR staging: 64 x 68 fp32 = 17408 B
#define SM_BI   52224        // b_i (64 f)
#define SM_BJ   52480        // b_j (64 f)
#define SM_SEG  52736        // 64 ints
#define SM_TOTAL 52992

__device__ __forceinline__ float tanh_fast(float v) {
    float r;
    asm("tanh.approx.f32 %0, %1;" : "=f"(r) : "f"(v));
    return r;
}
__device__ __forceinline__ unsigned int smem_u32(const void* p) {
    unsigned int a;
    asm("{ .reg .u64 t; cvta.to.shared.u64 t, %1; cvt.u32.u64 %0, t; }" : "=r"(a) : "l"(p));
    return a;
}

__global__ void zero_pooled_kernel(int n) {
    for (int i = blockIdx.x * blockDim.x + threadIdx.x; i < n; i += gridDim.x * blockDim.x)
        g_pooled[i] = 0.0f;
}

extern __shared__ char smc[];

__global__ __launch_bounds__(256, 1) void node_mma_kernel(
    const float* __restrict__ x, const float* __restrict__ h,
    const float* __restrict__ W_i, const float* __restrict__ b_i,
    const float* __restrict__ W_j, const float* __restrict__ b_j,
    const int* __restrict__ seg, int N, int ntiles)
{
    const int tid  = threadIdx.x;
    const int w    = tid >> 5, lane = tid & 31;
    const int wm   = w >> 2;          // 0..1 : node-row block of 32
    const int wn   = w & 3;           // 0..3 : B-col block of 32
    const int lr   = lane >> 2;       // groupID 0..7
    const int lc   = lane & 3;        // 0..3

    float* srr = (float*)(smc + SM_RR);
    float* sbi = (float*)(smc + SM_BI);
    float* sbj = (float*)(smc + SM_BJ);
    int*  sseg = (int*)(smc + SM_SEG);

    if (tid < 64) {
        sbi[tid] = b_i[tid];
        sbj[tid] = b_j[tid];
    }

    // ---- Weight-stationary B fragments (fp16), once per CTA ----
    // Logical B[n][k], n in [0,128): even n -> W_i col n/2 (k 0..127),
    //                                odd n  -> W_j col n/2 (k<64 else 0).
    // m16n8k16 B frag: reg i holds halves (k0,k0+1) at k0 = ks*16 + lc*2 + i*8, col n = base+lr.
    unsigned int Bf[4][8][2];
#pragma unroll
    for (int nf = 0; nf < 4; nf++) {
        const int n = wn * 32 + nf * 8 + lr;
        const int pcol = n >> 1;
        const bool isP = (n & 1) == 0;
#pragma unroll
        for (int ks = 0; ks < 8; ks++) {
#pragma unroll
            for (int i = 0; i < 2; i++) {
                const int k0 = ks * 16 + lc * 2 + i * 8;
                float v0, v1;
                if (isP) {
                    v0 = W_i[k0 * 64 + pcol];
                    v1 = W_i[(k0 + 1) * 64 + pcol];
                } else if (k0 < 64) {
                    v0 = W_j[k0 * 64 + pcol];
                    v1 = W_j[(k0 + 1) * 64 + pcol];
                } else {
                    v0 = 0.0f; v1 = 0.0f;
                }
                __half2 hv = __floats2half2_rn(v0, v1);
                Bf[nf][ks][i] = *(unsigned int*)&hv;
            }
        }
    }

    // ---- register-staged tile loaders ----
    float4 st[8];
    auto ldg_tile = [&](int tile) {
        const int base = tile * NT;
#pragma unroll
        for (int j = 0; j < 8; j++) {
            const int idx = tid + j * 256;          // 2048 float4 slots
            const int n = idx >> 5, kc = (idx & 31) << 2;
            const int gn = base + n;
            if (tile < ntiles && gn < N) {
                const float* src = (kc < 64) ? (h + (size_t)gn * 64 + kc)
                                             : (x + (size_t)gn * 64 + (kc - 64));
                st[j] = *(const float4*)src;
            } else {
                st[j] = make_float4(0.f, 0.f, 0.f, 0.f);
            }
        }
    };
    auto sts_tile = [&](int buf) {
        char* ab = smc + (buf ? SM_A1 : SM_A0);
#pragma unroll
        for (int j = 0; j < 8; j++) {
            const int idx = tid + j * 256;
            const int n = idx >> 5, kc = (idx & 31) << 2;
            __half2 lo = __floats2half2_rn(st[j].x, st[j].y);
            __half2 hi = __floats2half2_rn(st[j].z, st[j].w);
            uint2 v;
            v.x = *(unsigned int*)&lo;
            v.y = *(unsigned int*)&hi;
            *(uint2*)(ab + (n * AST + kc) * 2) = v;
        }
    };

    // Prologue: tile0 -> buf0; tile1 -> regs
    ldg_tile(blockIdx.x);
    sts_tile(0);
    ldg_tile(blockIdx.x + gridDim.x);
    __syncthreads();   // covers sbi/sbj + buf0

    const int lrow = lane & 15;                // ldmatrix row within 16
    const int lcol8 = (lane >> 4) << 3;        // ldmatrix col-half offset

    for (int it = 0;; it++) {
        const int tile = blockIdx.x + it * gridDim.x;
        if (tile >= ntiles) break;
        const int buf = it & 1;
        const char* sA = smc + (buf ? SM_A1 : SM_A0);

        // Stage segment ids for this tile
        if (tid < NT) {
            const int gn = tile * NT + tid;
            sseg[tid] = (gn < N) ? seg[gn] : -1;
        }

        // ---- GEMM: rows [wm*32,+32) x interleaved cols [wn*32,+32) ----
        float C[2][4][4];
#pragma unroll
        for (int mf = 0; mf < 2; mf++)
#pragma unroll
            for (int nf = 0; nf < 4; nf++)
#pragma unroll
                for (int q = 0; q < 4; q++) C[mf][nf][q] = 0.0f;

#pragma unroll
        for (int ks = 0; ks < 8; ks++) {
            unsigned int a[2][4];
#pragma unroll
            for (int mf = 0; mf < 2; mf++) {
                const unsigned int addr = smem_u32(
                    sA + ((wm * 32 + mf * 16 + lrow) * AST + ks * 16 + lcol8) * 2);
                asm volatile(
                    "ldmatrix.sync.aligned.m8n8.x4.shared.b16 {%0,%1,%2,%3}, [%4];"
                    : "=r"(a[mf][0]), "=r"(a[mf][1]), "=r"(a[mf][2]), "=r"(a[mf][3])
                    : "r"(addr));
            }
#pragma unroll
            for (int nf = 0; nf < 4; nf++)
#pragma unroll
                for (int mf = 0; mf < 2; mf++)
                    asm volatile(
                        "mma.sync.aligned.m16n8k16.row.col.f32.f16.f16.f32 "
                        "{%0,%1,%2,%3}, {%4,%5,%6,%7}, {%8,%9}, {%0,%1,%2,%3};"
                        : "+f"(C[mf][nf][0]), "+f"(C[mf][nf][1]),
                          "+f"(C[mf][nf][2]), "+f"(C[mf][nf][3])
                        : "r"(a[mf][0]), "r"(a[mf][1]), "r"(a[mf][2]), "r"(a[mf][3]),
                          "r"(Bf[nf][ks][0]), "r"(Bf[nf][ks][1]));
        }

        // STS tile it+1 into the other buffer (was consumed in it-1; sync'd)
        sts_tile(buf ^ 1);
        // Prefetch tile it+2 into regs (DRAM latency hides under epilogue)
        ldg_tile(blockIdx.x + (it + 2) * gridDim.x);

        // ---- Epilogue in registers: (c_even, c_odd) = (P, J) same node/col ----
#pragma unroll
        for (int nf = 0; nf < 4; nf++) {
            const int pcol = wn * 16 + nf * 4 + lc;
            const float bi = sbi[pcol], bj = sbj[pcol];
#pragma unroll
            for (int mf = 0; mf < 2; mf++) {
                const int r0 = wm * 32 + mf * 16 + lr;
#pragma unroll
                for (int rp = 0; rp < 2; rp++) {
                    const float P = C[mf][nf][rp * 2] + bi;
                    const float J = C[mf][nf][rp * 2 + 1] + bj;
                    const float iv = tanh_fast(P);
                    const float s = fmaf(tanh_fast(0.5f * iv), 0.5f, 0.5f); // sigmoid
                    srr[(r0 + rp * 8) * 68 + pcol] = s * fmaxf(J, 0.0f);
                }
            }
        }
        __syncthreads();

        // ---- Sorted-segment run-length reduce: thread (r,c) sums 16 nodes ----
        {
            const int c = tid & 63, r = tid >> 6;
            const int n0 = r * 16;
            float acc = 0.0f;
            int cur = sseg[n0];
#pragma unroll 4
            for (int n = n0; n < n0 + 16; n++) {
                const int s = sseg[n];
                if (s != cur) {
                    if (cur >= 0) atomicAdd(&g_pooled[cur * DD + c], acc);
                    acc = 0.0f;
                    cur = s;
                }
                acc += srr[n * 68 + c];
            }
            if (cur >= 0) atomicAdd(&g_pooled[cur * DD + c], acc);
        }
        __syncthreads();   // srr free + buf^1 visible for next iter's MMA
    }
}

// Per-graph readout: BN(inference) -> Dense(64->256)+ReLU -> Dense(256->1)
__global__ void readout_kernel(
    const float* __restrict__ gamma, const float* __restrict__ beta,
    const float* __restrict__ mov_mean, const float* __restrict__ mov_var,
    const float* __restrict__ W_h1, const float* __restrict__ b_h1,
    const float* __restrict__ W_out, const float* __restrict__ b_out,
    float* __restrict__ out)
{
    __shared__ float bn[DD];
    __shared__ float warp_part[8];
    const int g = blockIdx.x;
    const int t = threadIdx.x;

    if (t < DD) {
        const float p = g_pooled[g * DD + t];
        bn[t] = (p - mov_mean[t]) * rsqrtf(mov_var[t] + BN_EPS) * gamma[t] + beta[t];
    }
    __syncthreads();

    float y = 0.0f;
#pragma unroll 8
    for (int d = 0; d < DD; d++)
        y = fmaf(bn[d], W_h1[d * HH + t], y);
    y = fmaxf(y + b_h1[t], 0.0f);

    float v = y * W_out[t];
#pragma unroll
    for (int o = 16; o > 0; o >>= 1) v += __shfl_xor_sync(0xffffffffu, v, o);
    if ((t & 31) == 0) warp_part[t >> 5] = v;
    __syncthreads();
    if (t < 32) {
        float s = (t < 8) ? warp_part[t] : 0.0f;
#pragma unroll
        for (int o = 4; o > 0; o >>= 1) s += __shfl_xor_sync(0xffffffffu, s, o);
        if (t == 0) out[g] = s + b_out[0];
    }
}

extern "C" void kernel_launch(void* const* d_in, const int* in_sizes, int n_in,
                              void* d_out, int out_size)
{
    const float* x        = (const float*)d_in[0];
    const float* h        = (const float*)d_in[1];
    const float* W_i      = (const float*)d_in[2];
    const float* b_i      = (const float*)d_in[3];
    const float* W_j      = (const float*)d_in[4];
    const float* b_j      = (const float*)d_in[5];
    const float* gamma    = (const float*)d_in[6];
    const float* beta     = (const float*)d_in[7];
    const float* mov_mean = (const float*)d_in[8];
    const float* mov_var  = (const float*)d_in[9];
    const float* W_h1     = (const float*)d_in[10];
    const float* b_h1     = (const float*)d_in[11];
    const float* W_out    = (const float*)d_in[12];
    const float* b_out    = (const float*)d_in[13];
    const int*   seg      = (const int*)d_in[14];

    const int N = in_sizes[14];
    const int G = out_size;
    const int ntiles = (N + NT - 1) / NT;

    zero_pooled_kernel<<<256, 256>>>(G * DD);

    cudaFuncSetAttribute(node_mma_kernel, cudaFuncAttributeMaxDynamicSharedMemorySize,
                         SM_TOTAL);
    int grid = 148;
    if (grid > ntiles) grid = ntiles;
    node_mma_kernel<<<grid, 256, SM_TOTAL>>>(x, h, W_i, b_i, W_j, b_j, seg, N, ntiles);

    readout_kernel<<<G, 256>>>(gamma, beta, mov_mean, mov_var, W_h1, b_h1, W_out, b_out,
                               (float*)d_out);
}

// round 6
// speedup vs baseline: 3.9581x; 1.1148x over previous
#include <cuda_runtime.h>
#include <cuda_fp16.h>

#define DD 64
#define HH 256
#define MAXG 4096
#define BN_EPS 1e-3f
#define NT 64            // nodes per tile (GEMM M)
#define AST 136          // A smem row stride in halves (128 + 8 pad -> 272B)

__device__ float g_pooled[MAXG * DD];

// ---------- shared memory byte map (dynamic) ----------
#define SM_A0   0            // A buf 0: 64 x 136 fp16 = 17408 B
#define SM_A1   17408        // A buf 1
#define SM_RR   34816        // RR staging: 64 x 68 fp32 = 17408 B
#define SM_BI   52224        // b_i (64 f)
#define SM_BJ   52480        // b_j (64 f)
#define SM_SEG  52736        // 64 ints
#define SM_TOTAL 52992

__device__ __forceinline__ float tanh_fast(float v) {
    float r;
    asm("tanh.approx.f32 %0, %1;" : "=f"(r) : "f"(v));
    return r;
}
// sigmoid(t) for t in [-1,1]: odd Taylor poly, |err| < 3e-5 (no second MUFU)
__device__ __forceinline__ float sigmoid_unit(float t) {
    const float t2 = t * t;
    float p = fmaf(t2, -2.108134920634921e-4f, 2.0833333333e-3f);
    p = fmaf(t2, p, -2.0833333333e-2f);
    p = fmaf(t2, p, 0.25f);
    return fmaf(t, p, 0.5f);
}
__device__ __forceinline__ unsigned int smem_u32(const void* p) {
    unsigned int a;
    asm("{ .reg .u64 t; cvta.to.shared.u64 t, %1; cvt.u32.u64 %0, t; }" : "=r"(a) : "l"(p));
    return a;
}

__global__ void zero_pooled_kernel(int n) {
    for (int i = blockIdx.x * blockDim.x + threadIdx.x; i < n; i += gridDim.x * blockDim.x)
        g_pooled[i] = 0.0f;
}

extern __shared__ char smc[];

__global__ __launch_bounds__(256, 2) void node_mma_kernel(
    const float* __restrict__ x, const float* __restrict__ h,
    const float* __restrict__ W_i, const float* __restrict__ b_i,
    const float* __restrict__ W_j, const float* __restrict__ b_j,
    const int* __restrict__ seg, int N, int ntiles)
{
    const int tid  = threadIdx.x;
    const int w    = tid >> 5, lane = tid & 31;   // warp w owns interleaved cols [16w,16w+16)
    const int lr   = lane >> 2;       // groupID 0..7
    const int lc   = lane & 3;        // 0..3

    float* srr = (float*)(smc + SM_RR);
    float* sbi = (float*)(smc + SM_BI);
    float* sbj = (float*)(smc + SM_BJ);
    int*  sseg = (int*)(smc + SM_SEG);

    if (tid < 64) {
        sbi[tid] = b_i[tid];
        sbj[tid] = b_j[tid];
    }

    // ---- Weight-stationary B fragments (fp16), col-owned per warp (no dup) ----
    // Logical B[n][k], n in [0,128): even n -> W_i col n/2, odd n -> W_j col n/2 (k<64 else 0).
    // Warp w covers n in [w*16, w*16+16) = nf blocks {0,1} of 8 cols.
    unsigned int Bf[2][8][2];
#pragma unroll
    for (int nf = 0; nf < 2; nf++) {
        const int n = w * 16 + nf * 8 + lr;
        const int pcol = n >> 1;
        const bool isP = (n & 1) == 0;
#pragma unroll
        for (int ks = 0; ks < 8; ks++) {
#pragma unroll
            for (int i = 0; i < 2; i++) {
                const int k0 = ks * 16 + lc * 2 + i * 8;
                float v0, v1;
                if (isP) {
                    v0 = W_i[k0 * 64 + pcol];
                    v1 = W_i[(k0 + 1) * 64 + pcol];
                } else if (k0 < 64) {
                    v0 = W_j[k0 * 64 + pcol];
                    v1 = W_j[(k0 + 1) * 64 + pcol];
                } else {
                    v0 = 0.0f; v1 = 0.0f;
                }
                __half2 hv = __floats2half2_rn(v0, v1);
                Bf[nf][ks][i] = *(unsigned int*)&hv;
            }
        }
    }

    // ---- register-staged tile loaders (convert to half2 at load time) ----
    uint2 stc[8];
    auto ldg_tile = [&](int tile) {
        const int base = tile * NT;
#pragma unroll
        for (int j = 0; j < 8; j++) {
            const int idx = tid + j * 256;          // 2048 float4 slots
            const int n = idx >> 5, kc = (idx & 31) << 2;
            const int gn = base + n;
            float4 v = make_float4(0.f, 0.f, 0.f, 0.f);
            if (tile < ntiles && gn < N) {
                const float* src = (kc < 64) ? (h + (size_t)gn * 64 + kc)
                                             : (x + (size_t)gn * 64 + (kc - 64));
                v = *(const float4*)src;
            }
            __half2 lo = __floats2half2_rn(v.x, v.y);
            __half2 hi = __floats2half2_rn(v.z, v.w);
            stc[j].x = *(unsigned int*)&lo;
            stc[j].y = *(unsigned int*)&hi;
        }
    };
    auto sts_tile = [&](int buf) {
        char* ab = smc + (buf ? SM_A1 : SM_A0);
#pragma unroll
        for (int j = 0; j < 8; j++) {
            const int idx = tid + j * 256;
            const int n = idx >> 5, kc = (idx & 31) << 2;
            *(uint2*)(ab + (n * AST + kc) * 2) = stc[j];
        }
    };

    // Prologue: tile0 -> buf0; tile1 -> regs
    ldg_tile(blockIdx.x);
    sts_tile(0);
    ldg_tile(blockIdx.x + gridDim.x);
    __syncthreads();   // covers sbi/sbj + buf0

    const int lrow = lane & 15;                // ldmatrix row within 16
    const int lcol8 = (lane >> 4) << 3;        // ldmatrix col-half offset

    for (int it = 0;; it++) {
        const int tile = blockIdx.x + it * gridDim.x;
        if (tile >= ntiles) break;
        const int buf = it & 1;
        const char* sA = smc + (buf ? SM_A1 : SM_A0);

        // Stage segment ids for this tile
        if (tid < NT) {
            const int gn = tile * NT + tid;
            sseg[tid] = (gn < N) ? seg[gn] : -1;
        }

        // ---- GEMM: all 64 rows x this warp's 16 interleaved cols ----
        float C[4][2][4];
#pragma unroll
        for (int mf = 0; mf < 4; mf++)
#pragma unroll
            for (int nf = 0; nf < 2; nf++)
#pragma unroll
                for (int q = 0; q < 4; q++) C[mf][nf][q] = 0.0f;

#pragma unroll
        for (int ks = 0; ks < 8; ks++) {
#pragma unroll
            for (int mf = 0; mf < 4; mf++) {
                unsigned int a[4];
                const unsigned int addr = smem_u32(
                    sA + ((mf * 16 + lrow) * AST + ks * 16 + lcol8) * 2);
                asm volatile(
                    "ldmatrix.sync.aligned.m8n8.x4.shared.b16 {%0,%1,%2,%3}, [%4];"
                    : "=r"(a[0]), "=r"(a[1]), "=r"(a[2]), "=r"(a[3])
                    : "r"(addr));
#pragma unroll
                for (int nf = 0; nf < 2; nf++)
                    asm volatile(
                        "mma.sync.aligned.m16n8k16.row.col.f32.f16.f16.f32 "
                        "{%0,%1,%2,%3}, {%4,%5,%6,%7}, {%8,%9}, {%0,%1,%2,%3};"
                        : "+f"(C[mf][nf][0]), "+f"(C[mf][nf][1]),
                          "+f"(C[mf][nf][2]), "+f"(C[mf][nf][3])
                        : "r"(a[0]), "r"(a[1]), "r"(a[2]), "r"(a[3]),
                          "r"(Bf[nf][ks][0]), "r"(Bf[nf][ks][1]));
            }
        }

        // STS tile it+1 into the other buffer (consumed in it-1; sync'd)
        sts_tile(buf ^ 1);
        // Prefetch tile it+2 into regs (DRAM latency hides under epilogue)
        ldg_tile(blockIdx.x + (it + 2) * gridDim.x);

        // ---- Epilogue in registers: (c_even, c_odd) = (P, J) same node/col ----
#pragma unroll
        for (int nf = 0; nf < 2; nf++) {
            const int pcol = w * 8 + nf * 4 + lc;
            const float bi = sbi[pcol], bj = sbj[pcol];
#pragma unroll
            for (int mf = 0; mf < 4; mf++) {
                const int r0 = mf * 16 + lr;
#pragma unroll
                for (int rp = 0; rp < 2; rp++) {
                    const float P = C[mf][nf][rp * 2] + bi;
                    const float J = C[mf][nf][rp * 2 + 1] + bj;
                    const float s = sigmoid_unit(tanh_fast(P));
                    srr[(r0 + rp * 8) * 68 + pcol] = s * fmaxf(J, 0.0f);
                }
            }
        }
        __syncthreads();

        // ---- Sorted-segment run-length reduce: thread (r,c) sums 16 nodes ----
        {
            const int c = tid & 63, r = tid >> 6;
            const int n0 = r * 16;
            float acc = 0.0f;
            int cur = sseg[n0];
#pragma unroll 4
            for (int n = n0; n < n0 + 16; n++) {
                const int s = sseg[n];
                if (s != cur) {
                    if (cur >= 0) atomicAdd(&g_pooled[cur * DD + c], acc);
                    acc = 0.0f;
                    cur = s;
                }
                acc += srr[n * 68 + c];
            }
            if (cur >= 0) atomicAdd(&g_pooled[cur * DD + c], acc);
        }
        __syncthreads();   // srr free + buf^1 visible for next iter's MMA
    }
}

// Per-graph readout: BN(inference) -> Dense(64->256)+ReLU -> Dense(256->1)
__global__ void readout_kernel(
    const float* __restrict__ gamma, const float* __restrict__ beta,
    const float* __restrict__ mov_mean, const float* __restrict__ mov_var,
    const float* __restrict__ W_h1, const float* __restrict__ b_h1,
    const float* __restrict__ W_out, const float* __restrict__ b_out,
    float* __restrict__ out)
{
    __shared__ float bn[DD];
    __shared__ float warp_part[8];
    const int g = blockIdx.x;
    const int t = threadIdx.x;

    if (t < DD) {
        const float p = g_pooled[g * DD + t];
        bn[t] = (p - mov_mean[t]) * rsqrtf(mov_var[t] + BN_EPS) * gamma[t] + beta[t];
    }
    __syncthreads();

    float y = 0.0f;
#pragma unroll 8
    for (int d = 0; d < DD; d++)
        y = fmaf(bn[d], W_h1[d * HH + t], y);
    y = fmaxf(y + b_h1[t], 0.0f);

    float v = y * W_out[t];
#pragma unroll
    for (int o = 16; o > 0; o >>= 1) v += __shfl_xor_sync(0xffffffffu, v, o);
    if ((t & 31) == 0) warp_part[t >> 5] = v;
    __syncthreads();
    if (t < 32) {
        float s = (t < 8) ? warp_part[t] : 0.0f;
#pragma unroll
        for (int o = 4; o > 0; o >>= 1) s += __shfl_xor_sync(0xffffffffu, s, o);
        if (t == 0) out[g] = s + b_out[0];
    }
}

extern "C" void kernel_launch(void* const* d_in, const int* in_sizes, int n_in,
                              void* d_out, int out_size)
{
    const float* x        = (const float*)d_in[0];
    const float* h        = (const float*)d_in[1];
    const float* W_i      = (const float*)d_in[2];
    const float* b_i      = (const float*)d_in[3];
    const float* W_j      = (const float*)d_in[4];
    const float* b_j      = (const float*)d_in[5];
    const float* gamma    = (const float*)d_in[6];
    const float* beta     = (const float*)d_in[7];
    const float* mov_mean = (const float*)d_in[8];
    const float* mov_var  = (const float*)d_in[9];
    const float* W_h1     = (const float*)d_in[10];
    const float* b_h1     = (const float*)d_in[11];
    const float* W_out    = (const float*)d_in[12];
    const float* b_out    = (const float*)d_in[13];
    const int*   seg      = (const int*)d_in[14];

    const int N = in_sizes[14];
    const int G = out_size;
    const int ntiles = (N + NT - 1) / NT;

    zero_pooled_kernel<<<256, 256>>>(G * DD);

    cudaFuncSetAttribute(node_mma_kernel, cudaFuncAttributeMaxDynamicSharedMemorySize,
                         SM_TOTAL);
    int grid = 296;
    if (grid > ntiles) grid = ntiles;
    node_mma_kernel<<<grid, 256, SM_TOTAL>>>(x, h, W_i, b_i, W_j, b_j, seg, N, ntiles);

    readout_kernel<<<G, 256>>>(gamma, beta, mov_mean, mov_var, W_h1, b_h1, W_out, b_out,
                               (float*)d_out);
}